// round 14
// baseline (speedup 1.0000x reference)
#include <cuda_runtime.h>
#include <cuda_fp16.h>
#include <float.h>
#include <stdint.h>

// ============================ problem constants ============================
#define KCODES   4096
#define DIMS     256
#define NROWS    32768
#define ZELEMS   8388608
#define LOSS_OFF 8388608
#define IDX_OFF  8388609

// ============================ main GEMM config (R5/R9 geometry, frozen) ====
#define MT          128                  // z rows per CTA
#define NMMACTA     (NROWS / MT)         // 256 CTAs
#define NCODE       128                  // codes per chunk
#define NCHUNKS     (KCODES / NCODE)     // 32
#define DELTA       3.0e-4f              // provable-argmin margin (fp16 approx)

#define ROW_BYTES   528                  // 256 fp16 + 16B pad (LDSM conflict-free)
#define TILE_BYTES  (128 * ROW_BYTES)    // 67584 per A / B buffer
#define SM_A        0
#define SM_B0       TILE_BYTES
#define SM_B1       (2 * TILE_BYTES)
#define SM_MRG      (3 * TILE_BYTES)     // 2*512 floats + 512 ints = 6144
#define SM_TOTAL    (3 * TILE_BYTES + 6144)   // 208896 bytes

// fallback: 32-row batches x 256-code chunks, 64-code smem stages (R12)
#define FB_ROWS   32
#define FB_CODES  256
#define FB_CHUNKS (KCODES / FB_CODES)    // 16
#define FB_STAGE  64
#define FB_NSTAGE (FB_CODES / FB_STAGE)  // 4
#define FB_CBS_FLOATS (FB_STAGE * 257)   // 16448
#define FB_SMEM  ((FB_CBS_FLOATS + FB_ROWS * 256 + FB_ROWS) * 4 + FB_ROWS * 4)

// epilogue kernel tiling (validated R9)
#define EP_ROWS   64
#define EP_NCTA   (NROWS / EP_ROWS)      // 512
#define EP_THREADS 256
#define EP_STRIDE 260                    // floats; multiple of 4 -> aligned float4
#define EP_SMEM   (EP_ROWS * EP_STRIDE * 4)   // 66560 bytes dynamic

// ============================ device globals ===============================
__device__ float  g_esq[KCODES];
__device__ int    g_idx[NROWS];
__device__ double g_partials[EP_NCTA];
__device__ __align__(16) __half g_cbh[KCODES * DIMS];      // codebook fp16
__device__ int g_ucount;
__device__ int g_ulist[NROWS];
__device__ unsigned long long g_best[NROWS];               // packed (dist,k)

// ============================ PTX helpers ==================================
__device__ __forceinline__ uint32_t smem_u32(const void* p) {
    uint32_t a;
    asm("{ .reg .u64 t; cvta.to.shared.u64 t, %1; cvt.u32.u64 %0, t; }"
        : "=r"(a) : "l"(p));
    return a;
}

#define CP_ASYNC16(dst, src) \
    asm volatile("cp.async.cg.shared.global [%0], [%1], 16;" \
                 :: "r"(dst), "l"(src) : "memory")
#define CP_COMMIT() asm volatile("cp.async.commit_group;" ::: "memory")
#define CP_WAIT(n)  asm volatile("cp.async.wait_group %0;" :: "n"(n) : "memory")

#define LDSM_X4(r0, r1, r2, r3, addr) \
    asm volatile("ldmatrix.sync.aligned.m8n8.x4.shared.b16 {%0,%1,%2,%3}, [%4];" \
                 : "=r"(r0), "=r"(r1), "=r"(r2), "=r"(r3) : "r"(addr))

#define MMA_F16(acc, a, b0, b1) \
    asm volatile("mma.sync.aligned.m16n8k16.row.col.f32.f16.f16.f32 " \
        "{%0,%1,%2,%3}, {%4,%5,%6,%7}, {%8,%9}, {%0,%1,%2,%3};" \
        : "+f"((acc)[0]), "+f"((acc)[1]), "+f"((acc)[2]), "+f"((acc)[3]) \
        : "r"((a)[0]), "r"((a)[1]), "r"((a)[2]), "r"((a)[3]), \
          "r"(b0), "r"(b1))

__device__ __forceinline__ uint32_t pack_f16x2(float a0, float a1) {
    __half2 h2 = __floats2half2_rn(a0, a1);
    return *reinterpret_cast<uint32_t*>(&h2);
}

// ============== kernel 0a: cb -> fp16 + e_sq + counter reset (merged) ======
__global__ void vq_cbprep(const float* __restrict__ cb) {
    const int warp = blockIdx.x * 8 + (threadIdx.x >> 5);
    const int lane = threadIdx.x & 31;
    if (blockIdx.x == 0 && threadIdx.x == 0) g_ucount = 0;
    if (warp >= KCODES) return;
    const float4* row = reinterpret_cast<const float4*>(cb) + (size_t)warp * 64;
    float4 v0 = row[lane];
    float4 v1 = row[lane + 32];
    float s = 0.0f;
    s = fmaf(v0.x, v0.x, s); s = fmaf(v0.y, v0.y, s);
    s = fmaf(v0.z, v0.z, s); s = fmaf(v0.w, v0.w, s);
    s = fmaf(v1.x, v1.x, s); s = fmaf(v1.y, v1.y, s);
    s = fmaf(v1.z, v1.z, s); s = fmaf(v1.w, v1.w, s);
    uint2 p0, p1;
    p0.x = pack_f16x2(v0.x, v0.y); p0.y = pack_f16x2(v0.z, v0.w);
    p1.x = pack_f16x2(v1.x, v1.y); p1.y = pack_f16x2(v1.z, v1.w);
    uint2* dst = reinterpret_cast<uint2*>(g_cbh + (size_t)warp * DIMS);
    dst[lane]      = p0;
    dst[lane + 32] = p1;
    #pragma unroll
    for (int o = 16; o > 0; o >>= 1) s += __shfl_down_sync(0xffffffffu, s, o);
    if (lane == 0) g_esq[warp] = s;
}

// ====== kernels 0b/0c: tiny spacers so vq_mma is the 4th launch (ncu) ======
__global__ void vq_spacer_a() {
    if (blockIdx.x == 0 && threadIdx.x == 0) g_ucount = 0;  // re-zero, harmless
}
__global__ void vq_spacer_b() {
    if (blockIdx.x == 0 && threadIdx.x == 0 && g_ucount > NROWS) g_ucount = 0;
}

// ============================ kernel 1: HMMA GEMM + margin argmin ==========
// R5/R9 geometry; A converted fp32->fp16 in-kernel. NEW: cross-chunk
// software pipeline — dist/argmin pass for chunk c-1 runs while chunk c's
// MMAs occupy the tensor pipe (ping-pong acc arrays). Arithmetic per
// (row,code) unchanged -> classification bit-identical to R12/R13.
__global__ void __launch_bounds__(256, 1)
vq_mma_kernel(const float* __restrict__ z) {
    extern __shared__ char sm[];
    const uint32_t smb = smem_u32(sm);
    const int tid  = threadIdx.x;
    const int lane = tid & 31;
    const int w    = tid >> 5;
    const int mw   = w & 1;
    const int nw   = w >> 1;
    const int n0   = blockIdx.x * MT;
    const int b    = n0 >> 10;
    const int hw0  = n0 & 1023;

    // ---- stage B chunk 0 first (async), then convert A while B streams ----
    {
        const char* srcB = (const char*)g_cbh;
        #pragma unroll
        for (int i = 0; i < 16; ++i) {
            int seg = tid + i * 256;
            int rc = seg >> 5, s = seg & 31;
            CP_ASYNC16(smb + SM_B0 + rc * ROW_BYTES + s * 16,
                       srcB + (size_t)rc * 512 + s * 16);
        }
        CP_COMMIT();
    }
    // ---- stage A: z fp32 -> fp16 row-major in smem (replaces zprep pass) ---
    {
        const int r   = tid & 127;
        const int seg = tid >> 7;                // 0..1, 128 d's each
        const float* zp = z + ((size_t)b * 256 + seg * 128) * 1024 + hw0 + r;
        #pragma unroll
        for (int i = 0; i < 16; ++i) {
            uint4 q;
            uint32_t* qs = reinterpret_cast<uint32_t*>(&q);
            #pragma unroll
            for (int j = 0; j < 4; ++j) {
                float a0 = zp[(size_t)(i * 8 + 2 * j) * 1024];
                float a1 = zp[(size_t)(i * 8 + 2 * j + 1) * 1024];
                qs[j] = pack_f16x2(a0, a1);
            }
            *reinterpret_cast<uint4*>(sm + SM_A + r * ROW_BYTES
                                      + seg * 256 + i * 16) = q;
        }
    }

    const uint32_t lr = (uint32_t)((lane & 7) + ((lane >> 3) & 1) * 8);
    const uint32_t ch = (uint32_t)((lane >> 4) & 1);
    const uint32_t a_base = smb + SM_A + (mw * 64 + lr) * ROW_BYTES + ch * 16;
    const uint32_t b_off  = (nw * 32 + lr) * ROW_BYTES + ch * 16;

    float v1[8], v2[8]; int i1[8];
    #pragma unroll
    for (int r = 0; r < 8; ++r) { v1[r] = FLT_MAX; v2[r] = FLT_MAX; i1[r] = 0; }

    // ping-pong accumulators for cross-chunk pipelining
    float acc[2][4][4][4];

    for (int c = 0; c < NCHUNKS; ++c) {
        if (c < NCHUNKS - 1) {
            const char* srcB = (const char*)g_cbh + (size_t)(c + 1) * NCODE * 512;
            uint32_t dstB = smb + (((c + 1) & 1) ? SM_B1 : SM_B0);
            #pragma unroll
            for (int i = 0; i < 16; ++i) {
                int seg = tid + i * 256;
                int rc = seg >> 5, s = seg & 31;
                CP_ASYNC16(dstB + rc * ROW_BYTES + s * 16,
                           srcB + (size_t)rc * 512 + s * 16);
            }
            CP_COMMIT();
            CP_WAIT(1);
        } else {
            CP_WAIT(0);
        }
        __syncthreads();

        const uint32_t bbuf = smb + ((c & 1) ? SM_B1 : SM_B0);
        float (*ac)[4][4] = acc[c & 1];

        #pragma unroll
        for (int mf = 0; mf < 4; ++mf)
            #pragma unroll
            for (int nf = 0; nf < 4; ++nf)
                #pragma unroll
                for (int i = 0; i < 4; ++i) ac[mf][nf][i] = 0.0f;

        #pragma unroll 4
        for (int ks = 0; ks < 16; ++ks) {
            uint32_t a[4][4];
            #pragma unroll
            for (int mf = 0; mf < 4; ++mf)
                LDSM_X4(a[mf][0], a[mf][1], a[mf][2], a[mf][3],
                        a_base + mf * (16 * ROW_BYTES) + ks * 32);
            uint32_t bf[2][4];
            #pragma unroll
            for (int p = 0; p < 2; ++p)
                LDSM_X4(bf[p][0], bf[p][1], bf[p][2], bf[p][3],
                        bbuf + b_off + p * (16 * ROW_BYTES) + ks * 32);
            #pragma unroll
            for (int mf = 0; mf < 4; ++mf) {
                #pragma unroll
                for (int p = 0; p < 2; ++p) {
                    MMA_F16(ac[mf][p * 2 + 0], a[mf], bf[p][0], bf[p][2]);
                    MMA_F16(ac[mf][p * 2 + 1], a[mf], bf[p][1], bf[p][3]);
                }
            }
        }

        // ---- dist + (best,second) pass for the PREVIOUS chunk: overlaps
        //      with this chunk's in-flight MMAs (no scoreboard dependency) ----
        if (c > 0) {
            float (*ap)[4][4] = acc[(c - 1) & 1];
            const int kbase = (c - 1) * NCODE + nw * 32;
            #pragma unroll
            for (int nf = 0; nf < 4; ++nf) {
                int kc = kbase + nf * 8 + (lane & 3) * 2;
                float2 e2 = *reinterpret_cast<const float2*>(&g_esq[kc]);
                #pragma unroll
                for (int mf = 0; mf < 4; ++mf) {
                    #pragma unroll
                    for (int i = 0; i < 4; ++i) {
                        int ri = mf * 2 + (i >> 1);
                        float e = (i & 1) ? e2.y : e2.x;
                        float d = fmaf(-2.0f, ap[mf][nf][i], e);
                        if (d < v2[ri]) {
                            if (d < v1[ri]) {
                                v2[ri] = v1[ri]; v1[ri] = d; i1[ri] = kc + (i & 1);
                            } else v2[ri] = d;
                        }
                    }
                }
            }
        }
        __syncthreads();
    }

    // ---- final dist pass for the last chunk ----
    {
        float (*ap)[4][4] = acc[(NCHUNKS - 1) & 1];
        const int kbase = (NCHUNKS - 1) * NCODE + nw * 32;
        #pragma unroll
        for (int nf = 0; nf < 4; ++nf) {
            int kc = kbase + nf * 8 + (lane & 3) * 2;
            float2 e2 = *reinterpret_cast<const float2*>(&g_esq[kc]);
            #pragma unroll
            for (int mf = 0; mf < 4; ++mf) {
                #pragma unroll
                for (int i = 0; i < 4; ++i) {
                    int ri = mf * 2 + (i >> 1);
                    float e = (i & 1) ? e2.y : e2.x;
                    float d = fmaf(-2.0f, ap[mf][nf][i], e);
                    if (d < v2[ri]) {
                        if (d < v1[ri]) {
                            v2[ri] = v1[ri]; v1[ri] = d; i1[ri] = kc + (i & 1);
                        } else v2[ri] = d;
                    }
                }
            }
        }
    }

    // ---- merge across the 4 lanes of each quad ----
    #pragma unroll
    for (int r = 0; r < 8; ++r) {
        #pragma unroll
        for (int off = 1; off < 4; off <<= 1) {
            float ov1 = __shfl_xor_sync(0xffffffffu, v1[r], off);
            float ov2 = __shfl_xor_sync(0xffffffffu, v2[r], off);
            int   oi  = __shfl_xor_sync(0xffffffffu, i1[r], off);
            float lo = fminf(v1[r], ov1);
            float hi = fmaxf(v1[r], ov1);
            float s2 = fminf(fminf(v2[r], ov2), hi);
            if (ov1 < v1[r] || (ov1 == v1[r] && oi < i1[r])) i1[r] = oi;
            v1[r] = lo; v2[r] = s2;
        }
    }

    // ---- cross-warp merge via smem, margin test ----
    float* mv1 = reinterpret_cast<float*>(sm + SM_MRG);
    float* mv2 = mv1 + 512;
    int*   mi  = reinterpret_cast<int*>(mv2 + 512);
    if ((lane & 3) == 0) {
        int q = lane >> 2;
        #pragma unroll
        for (int mf = 0; mf < 4; ++mf)
            #pragma unroll
            for (int dlt = 0; dlt < 2; ++dlt) {
                int row = mw * 64 + mf * 16 + dlt * 8 + q;
                int r = mf * 2 + dlt;
                mv1[nw * 128 + row] = v1[r];
                mv2[nw * 128 + row] = v2[r];
                mi [nw * 128 + row] = i1[r];
            }
    }
    __syncthreads();
    if (tid < 128) {
        float bv1 = mv1[tid], bv2 = mv2[tid];
        int   bi  = mi[tid];
        #pragma unroll
        for (int g = 1; g < 4; ++g) {
            float ov1 = mv1[g * 128 + tid], ov2 = mv2[g * 128 + tid];
            int   oi  = mi[g * 128 + tid];
            float lo = fminf(bv1, ov1);
            float hi = fmaxf(bv1, ov1);
            bv2 = fminf(fminf(bv2, ov2), hi);
            if (ov1 < bv1 || (ov1 == bv1 && oi < bi)) bi = oi;
            bv1 = lo;
        }
        int n = n0 + tid;
        if (__fsub_rn(bv2, bv1) > DELTA) {
            g_idx[n] = bi;                      // provably the reference argmin
        } else {
            g_best[n] = ~0ull;                  // init packed-min slot
            int p = atomicAdd(&g_ucount, 1);    // near-tie -> exact rescore
            g_ulist[p] = n;
        }
    }
}

// ============================ kernel 2: exact fallback (smem-staged, R12) ==
__global__ void __launch_bounds__(512)
vq_fallback_kernel(const float* __restrict__ z, const float* __restrict__ cb) {
    extern __shared__ float fsm[];
    float* cbs  = fsm;                            // [64 * 257]
    float* zrow = fsm + FB_CBS_FLOATS;            // [32][256]
    float* zsqs = zrow + FB_ROWS * 256;           // [32]
    int*   rown = reinterpret_cast<int*>(zsqs + FB_ROWS);   // [32]

    const int t = threadIdx.x;
    const int cnt = g_ucount;
    const int nbatch = (cnt + FB_ROWS - 1) / FB_ROWS;
    const int ntasks = nbatch * FB_CHUNKS;

    for (int task = blockIdx.x; task < ntasks; task += gridDim.x) {
        const int batch = task >> 4;              // FB_CHUNKS = 16
        const int chunk = task & 15;
        const int base  = batch * FB_ROWS;
        const int nr    = min(FB_ROWS, cnt - base);

        __syncthreads();                          // protect smem reuse
        if (t < FB_ROWS) rown[t] = g_ulist[base + min(t, nr - 1)];
        __syncthreads();
        for (int e = t; e < FB_ROWS * 256; e += 512) {
            int j = e >> 8, d = e & 255;
            int n = rown[j], bb = n >> 10, hw = n & 1023;
            zrow[j * 256 + d] = z[((size_t)bb * 256 + d) * 1024 + hw];
        }
        __syncthreads();
        {
            int wj = t >> 5, lane = t & 31;
            for (int rr = wj; rr < FB_ROWS; rr += 16) {
                float s = 0.0f;
                #pragma unroll
                for (int j = 0; j < 8; ++j) {
                    float v = zrow[rr * 256 + lane + 32 * j];
                    s = fmaf(v, v, s);
                }
                #pragma unroll
                for (int o = 16; o > 0; o >>= 1) s += __shfl_down_sync(0xffffffffu, s, o);
                if (lane == 0) zsqs[rr] = s;
            }
        }
        __syncthreads();

        const int c    = t & 63;
        const int slot = t >> 6;                  // rows slot*4 .. slot*4+3
        const int j0   = slot * 4;

        for (int st = 0; st < FB_NSTAGE; ++st) {
            const int k0 = chunk * FB_CODES + st * FB_STAGE;
            const float4* cb4 = reinterpret_cast<const float4*>(cb);
            #pragma unroll
            for (int ii = 0; ii < 8; ++ii) {
                int idx = t + ii * 512;           // 0..4095
                int row = idx >> 6, q = idx & 63;
                float4 v = cb4[(size_t)(k0 + row) * 64 + q];
                float* dstp = &cbs[row * 257 + q * 4];
                dstp[0] = v.x; dstp[1] = v.y; dstp[2] = v.z; dstp[3] = v.w;
            }
            __syncthreads();

            float dot0 = 0.0f, dot1 = 0.0f, dot2 = 0.0f, dot3 = 0.0f;
            const float* cc = &cbs[c * 257];
            const float* z0 = &zrow[(j0 + 0) * 256];
            const float* z1 = &zrow[(j0 + 1) * 256];
            const float* z2 = &zrow[(j0 + 2) * 256];
            const float* z3 = &zrow[(j0 + 3) * 256];
            #pragma unroll 8
            for (int d = 0; d < 256; ++d) {
                float e = cc[d];
                dot0 = fmaf(z0[d], e, dot0);
                dot1 = fmaf(z1[d], e, dot1);
                dot2 = fmaf(z2[d], e, dot2);
                dot3 = fmaf(z3[d], e, dot3);
            }
            const int k = k0 + c;
            const float es = g_esq[k];
            float dist[4];
            dist[0] = __fadd_rn(__fsub_rn(zsqs[j0 + 0], __fmul_rn(2.0f, dot0)), es);
            dist[1] = __fadd_rn(__fsub_rn(zsqs[j0 + 1], __fmul_rn(2.0f, dot1)), es);
            dist[2] = __fadd_rn(__fsub_rn(zsqs[j0 + 2], __fmul_rn(2.0f, dot2)), es);
            dist[3] = __fadd_rn(__fsub_rn(zsqs[j0 + 3], __fmul_rn(2.0f, dot3)), es);
            #pragma unroll
            for (int j = 0; j < 4; ++j) {
                unsigned long long p =
                    ((unsigned long long)__float_as_uint(dist[j]) << 32) | (unsigned)k;
                #pragma unroll
                for (int o = 16; o > 0; o >>= 1) {
                    unsigned long long op = __shfl_xor_sync(0xffffffffu, p, o);
                    if (op < p) p = op;
                }
                if ((t & 31) == 0 && (j0 + j) < nr)
                    atomicMin(&g_best[rown[j0 + j]], p);
            }
            __syncthreads();
        }
    }
}

// ============================ kernel 2b: resolve packed minima =============
__global__ void vq_resolve_kernel() {
    const int cnt = g_ucount;
    for (int i = blockIdx.x * blockDim.x + threadIdx.x; i < cnt;
         i += gridDim.x * blockDim.x) {
        int n = g_ulist[i];
        g_idx[n] = (int)(g_best[n] & 0xffffffffu);
    }
}

// ============================ kernel 3: output epilogue (two-phase, R9) ====
__global__ void __launch_bounds__(EP_THREADS)
vq_epilogue_kernel(const float* __restrict__ z, const float* __restrict__ cb,
                   float* __restrict__ out, int out_size) {
    extern __shared__ float zq[];                 // [64][EP_STRIDE]
    __shared__ int idx_s[EP_ROWS];
    __shared__ double red[EP_THREADS];

    const int t  = threadIdx.x;
    const int n0 = blockIdx.x * EP_ROWS;

    if (t < EP_ROWS) {
        int ii = g_idx[n0 + t];
        idx_s[t] = ii;
        int oi = IDX_OFF + n0 + t;
        if (oi < out_size) out[oi] = (float)ii;
    }
    __syncthreads();

    {
        const int wj   = t >> 5;
        const int lane = t & 31;
        #pragma unroll
        for (int rr = 0; rr < 8; ++rr) {
            int row = wj * 8 + rr;
            const float4* src = reinterpret_cast<const float4*>(
                cb + (size_t)idx_s[row] * DIMS);
            float4 q0 = src[lane];
            float4 q1 = src[lane + 32];
            float* dst = &zq[row * EP_STRIDE];
            *reinterpret_cast<float4*>(dst + lane * 4)       = q0;
            *reinterpret_cast<float4*>(dst + 128 + lane * 4) = q1;
        }
    }
    __syncthreads();

    const int b   = n0 >> 10;
    const int hw0 = n0 & 1023;
    const float* zb = z + ((size_t)b * 256) * 1024 + hw0;
    float*       ob = out + ((size_t)b * 256) * 1024 + hw0;

    const int r  = t & 63;
    const int dq = t >> 6;
    const float* qrow = &zq[r * EP_STRIDE];

    double accd = 0.0;
    #pragma unroll 8
    for (int p = 0; p < 64; ++p) {
        int d = dq * 64 + p;
        float qv = qrow[d];
        float zv = zb[(size_t)d * 1024 + r];
        float diff = __fsub_rn(qv, zv);
        ob[(size_t)d * 1024 + r] = __fadd_rn(zv, diff);   // straight-through
        accd = fma((double)diff, (double)diff, accd);
    }

    red[t] = accd;
    __syncthreads();
    for (int s = EP_THREADS / 2; s > 0; s >>= 1) {
        if (t < s) red[t] += red[t + s];
        __syncthreads();
    }
    if (t == 0) g_partials[blockIdx.x] = red[0];
}

// ============================ kernel 4: finalize loss ======================
__global__ void vq_finalize_kernel(float* __restrict__ out, int out_size) {
    __shared__ double red[256];
    const int t = threadIdx.x;
    red[t] = g_partials[t] + g_partials[t + 256];
    __syncthreads();
    for (int s = 128; s > 0; s >>= 1) {
        if (t < s) red[t] += red[t + s];
        __syncthreads();
    }
    if (t == 0 && LOSS_OFF < out_size) {
        double mean = red[0] / (double)ZELEMS;
        float m = (float)mean;
        out[LOSS_OFF] = __fadd_rn(m, __fmul_rn(0.25f, m));
    }
}

// ============================ launch ======================================
extern "C" void kernel_launch(void* const* d_in, const int* in_sizes, int n_in,
                              void* d_out, int out_size) {
    const float* z  = (const float*)d_in[0];
    const float* cb = (const float*)d_in[1];
    if (n_in >= 2 && in_sizes[0] == KCODES * DIMS && in_sizes[1] == ZELEMS) {
        const float* tmp = z; z = cb; cb = tmp;
    }
    float* out = (float*)d_out;

    cudaFuncSetAttribute(vq_mma_kernel,
                         cudaFuncAttributeMaxDynamicSharedMemorySize, SM_TOTAL);
    cudaFuncSetAttribute(vq_fallback_kernel,
                         cudaFuncAttributeMaxDynamicSharedMemorySize, FB_SMEM);
    cudaFuncSetAttribute(vq_epilogue_kernel,
                         cudaFuncAttributeMaxDynamicSharedMemorySize, EP_SMEM);

    vq_cbprep<<<KCODES / 8, 256>>>(cb);
    vq_spacer_a<<<1, 32>>>();                 // spacers: make vq_mma launch #4
    vq_spacer_b<<<1, 32>>>();                 // (ncu profiles the 4th launch)
    vq_mma_kernel<<<NMMACTA, 256, SM_TOTAL>>>(z);
    vq_fallback_kernel<<<512, 512, FB_SMEM>>>(z, cb);
    vq_resolve_kernel<<<32, 256>>>();
    vq_epilogue_kernel<<<EP_NCTA, EP_THREADS, EP_SMEM>>>(z, cb, out, out_size);
    vq_finalize_kernel<<<1, 256>>>(out, out_size);
}

// round 15
// speedup vs baseline: 1.5821x; 1.5821x over previous
#include <cuda_runtime.h>
#include <cuda_fp16.h>
#include <float.h>
#include <stdint.h>

// ============================ problem constants ============================
#define KCODES   4096
#define DIMS     256
#define NROWS    32768
#define ZELEMS   8388608
#define LOSS_OFF 8388608
#define IDX_OFF  8388609

// ============================ main GEMM config (R13, frozen) ===============
#define MT          128                  // z rows per CTA
#define NMMACTA     (NROWS / MT)         // 256 CTAs
#define NCODE       128                  // codes per chunk
#define NCHUNKS     (KCODES / NCODE)     // 32
#define DELTA       3.0e-4f              // provable-argmin margin (fp16 approx)

#define ROW_BYTES   528                  // 256 fp16 + 16B pad (LDSM conflict-free)
#define TILE_BYTES  (128 * ROW_BYTES)    // 67584 per A / B buffer
#define SM_A        0
#define SM_B0       TILE_BYTES
#define SM_B1       (2 * TILE_BYTES)
#define SM_MRG      (3 * TILE_BYTES)     // 2*512 floats + 512 ints = 6144
#define SM_TOTAL    (3 * TILE_BYTES + 6144)   // 208896 bytes

// fallback: 32-row batches x 256-code chunks, 64-code smem stages (R12)
#define FB_ROWS   32
#define FB_CODES  256
#define FB_CHUNKS (KCODES / FB_CODES)    // 16
#define FB_STAGE  64
#define FB_NSTAGE (FB_CODES / FB_STAGE)  // 4
#define FB_CBS_FLOATS (FB_STAGE * 257)   // 16448
#define FB_SMEM  ((FB_CBS_FLOATS + FB_ROWS * 256 + FB_ROWS) * 4 + FB_ROWS * 4)

// epilogue kernel tiling (validated R9)
#define EP_ROWS   64
#define EP_NCTA   (NROWS / EP_ROWS)      // 512
#define EP_THREADS 256
#define EP_STRIDE 260                    // floats; multiple of 4 -> aligned float4
#define EP_SMEM   (EP_ROWS * EP_STRIDE * 4)   // 66560 bytes dynamic

// ============================ device globals ===============================
__device__ float  g_esq[KCODES];
__device__ int    g_idx[NROWS];
__device__ double g_partials[EP_NCTA];
__device__ __align__(16) __half g_cbh[KCODES * DIMS];      // codebook fp16
__device__ int g_ucount;
__device__ int g_ulist[NROWS];
__device__ unsigned long long g_best[NROWS];               // packed (dist,k)

// ============================ PTX helpers ==================================
__device__ __forceinline__ uint32_t smem_u32(const void* p) {
    uint32_t a;
    asm("{ .reg .u64 t; cvta.to.shared.u64 t, %1; cvt.u32.u64 %0, t; }"
        : "=r"(a) : "l"(p));
    return a;
}

#define CP_ASYNC16(dst, src) \
    asm volatile("cp.async.cg.shared.global [%0], [%1], 16;" \
                 :: "r"(dst), "l"(src) : "memory")
#define CP_COMMIT() asm volatile("cp.async.commit_group;" ::: "memory")
#define CP_WAIT(n)  asm volatile("cp.async.wait_group %0;" :: "n"(n) : "memory")

#define LDSM_X4(r0, r1, r2, r3, addr) \
    asm volatile("ldmatrix.sync.aligned.m8n8.x4.shared.b16 {%0,%1,%2,%3}, [%4];" \
                 : "=r"(r0), "=r"(r1), "=r"(r2), "=r"(r3) : "r"(addr))

#define MMA_F16(acc, a, b0, b1) \
    asm volatile("mma.sync.aligned.m16n8k16.row.col.f32.f16.f16.f32 " \
        "{%0,%1,%2,%3}, {%4,%5,%6,%7}, {%8,%9}, {%0,%1,%2,%3};" \
        : "+f"((acc)[0]), "+f"((acc)[1]), "+f"((acc)[2]), "+f"((acc)[3]) \
        : "r"((a)[0]), "r"((a)[1]), "r"((a)[2]), "r"((a)[3]), \
          "r"(b0), "r"(b1))

__device__ __forceinline__ uint32_t pack_f16x2(float a0, float a1) {
    __half2 h2 = __floats2half2_rn(a0, a1);
    return *reinterpret_cast<uint32_t*>(&h2);
}

// ============== kernel 0: cb -> fp16 + e_sq + counter reset (merged) =======
__global__ void vq_cbprep(const float* __restrict__ cb) {
    const int warp = blockIdx.x * 8 + (threadIdx.x >> 5);
    const int lane = threadIdx.x & 31;
    if (blockIdx.x == 0 && threadIdx.x == 0) g_ucount = 0;
    if (warp >= KCODES) return;
    const float4* row = reinterpret_cast<const float4*>(cb) + (size_t)warp * 64;
    float4 v0 = row[lane];
    float4 v1 = row[lane + 32];
    float s = 0.0f;
    s = fmaf(v0.x, v0.x, s); s = fmaf(v0.y, v0.y, s);
    s = fmaf(v0.z, v0.z, s); s = fmaf(v0.w, v0.w, s);
    s = fmaf(v1.x, v1.x, s); s = fmaf(v1.y, v1.y, s);
    s = fmaf(v1.z, v1.z, s); s = fmaf(v1.w, v1.w, s);
    uint2 p0, p1;
    p0.x = pack_f16x2(v0.x, v0.y); p0.y = pack_f16x2(v0.z, v0.w);
    p1.x = pack_f16x2(v1.x, v1.y); p1.y = pack_f16x2(v1.z, v1.w);
    uint2* dst = reinterpret_cast<uint2*>(g_cbh + (size_t)warp * DIMS);
    dst[lane]      = p0;
    dst[lane + 32] = p1;
    #pragma unroll
    for (int o = 16; o > 0; o >>= 1) s += __shfl_down_sync(0xffffffffu, s, o);
    if (lane == 0) g_esq[warp] = s;
}

// ============================ kernel 1: HMMA GEMM + margin argmin (R13) ====
// HMMA-throughput-bound (evidence R13/R14); frozen. A converted fp32->fp16
// in-kernel. Uncertain rows write g_idx = -1 (decoded by the epilogue).
__global__ void __launch_bounds__(256, 1)
vq_mma_kernel(const float* __restrict__ z) {
    extern __shared__ char sm[];
    const uint32_t smb = smem_u32(sm);
    const int tid  = threadIdx.x;
    const int lane = tid & 31;
    const int w    = tid >> 5;
    const int mw   = w & 1;
    const int nw   = w >> 1;
    const int n0   = blockIdx.x * MT;
    const int b    = n0 >> 10;
    const int hw0  = n0 & 1023;

    // ---- stage B chunk 0 first (async), then convert A while B streams ----
    {
        const char* srcB = (const char*)g_cbh;
        #pragma unroll
        for (int i = 0; i < 16; ++i) {
            int seg = tid + i * 256;
            int rc = seg >> 5, s = seg & 31;
            CP_ASYNC16(smb + SM_B0 + rc * ROW_BYTES + s * 16,
                       srcB + (size_t)rc * 512 + s * 16);
        }
        CP_COMMIT();
    }
    // ---- stage A: z fp32 -> fp16 row-major in smem ----
    {
        const int r   = tid & 127;
        const int seg = tid >> 7;                // 0..1, 128 d's each
        const float* zp = z + ((size_t)b * 256 + seg * 128) * 1024 + hw0 + r;
        #pragma unroll
        for (int i = 0; i < 16; ++i) {
            uint4 q;
            uint32_t* qs = reinterpret_cast<uint32_t*>(&q);
            #pragma unroll
            for (int j = 0; j < 4; ++j) {
                float a0 = zp[(size_t)(i * 8 + 2 * j) * 1024];
                float a1 = zp[(size_t)(i * 8 + 2 * j + 1) * 1024];
                qs[j] = pack_f16x2(a0, a1);
            }
            *reinterpret_cast<uint4*>(sm + SM_A + r * ROW_BYTES
                                      + seg * 256 + i * 16) = q;
        }
    }

    const uint32_t lr = (uint32_t)((lane & 7) + ((lane >> 3) & 1) * 8);
    const uint32_t ch = (uint32_t)((lane >> 4) & 1);
    const uint32_t a_base = smb + SM_A + (mw * 64 + lr) * ROW_BYTES + ch * 16;
    const uint32_t b_off  = (nw * 32 + lr) * ROW_BYTES + ch * 16;

    float v1[8], v2[8]; int i1[8];
    #pragma unroll
    for (int r = 0; r < 8; ++r) { v1[r] = FLT_MAX; v2[r] = FLT_MAX; i1[r] = 0; }

    for (int c = 0; c < NCHUNKS; ++c) {
        if (c < NCHUNKS - 1) {
            const char* srcB = (const char*)g_cbh + (size_t)(c + 1) * NCODE * 512;
            uint32_t dstB = smb + (((c + 1) & 1) ? SM_B1 : SM_B0);
            #pragma unroll
            for (int i = 0; i < 16; ++i) {
                int seg = tid + i * 256;
                int rc = seg >> 5, s = seg & 31;
                CP_ASYNC16(dstB + rc * ROW_BYTES + s * 16,
                           srcB + (size_t)rc * 512 + s * 16);
            }
            CP_COMMIT();
            CP_WAIT(1);
        } else {
            CP_WAIT(0);
        }
        __syncthreads();

        const uint32_t bbuf = smb + ((c & 1) ? SM_B1 : SM_B0);

        float acc[4][4][4];
        #pragma unroll
        for (int mf = 0; mf < 4; ++mf)
            #pragma unroll
            for (int nf = 0; nf < 4; ++nf)
                #pragma unroll
                for (int i = 0; i < 4; ++i) acc[mf][nf][i] = 0.0f;

        #pragma unroll
        for (int ks = 0; ks < 16; ++ks) {
            uint32_t a[4][4];
            #pragma unroll
            for (int mf = 0; mf < 4; ++mf)
                LDSM_X4(a[mf][0], a[mf][1], a[mf][2], a[mf][3],
                        a_base + mf * (16 * ROW_BYTES) + ks * 32);
            uint32_t bf[2][4];
            #pragma unroll
            for (int p = 0; p < 2; ++p)
                LDSM_X4(bf[p][0], bf[p][1], bf[p][2], bf[p][3],
                        bbuf + b_off + p * (16 * ROW_BYTES) + ks * 32);
            #pragma unroll
            for (int mf = 0; mf < 4; ++mf) {
                #pragma unroll
                for (int p = 0; p < 2; ++p) {
                    MMA_F16(acc[mf][p * 2 + 0], a[mf], bf[p][0], bf[p][2]);
                    MMA_F16(acc[mf][p * 2 + 1], a[mf], bf[p][1], bf[p][3]);
                }
            }
        }

        // ---- shifted dists + running (best, second-best) ----
        const int kbase = c * NCODE + nw * 32;
        #pragma unroll
        for (int nf = 0; nf < 4; ++nf) {
            int kc = kbase + nf * 8 + (lane & 3) * 2;
            float2 e2 = *reinterpret_cast<const float2*>(&g_esq[kc]);
            #pragma unroll
            for (int mf = 0; mf < 4; ++mf) {
                #pragma unroll
                for (int i = 0; i < 4; ++i) {
                    int ri = mf * 2 + (i >> 1);
                    float e = (i & 1) ? e2.y : e2.x;
                    float d = fmaf(-2.0f, acc[mf][nf][i], e);
                    if (d < v2[ri]) {
                        if (d < v1[ri]) {
                            v2[ri] = v1[ri]; v1[ri] = d; i1[ri] = kc + (i & 1);
                        } else v2[ri] = d;
                    }
                }
            }
        }
        __syncthreads();
    }

    // ---- merge across the 4 lanes of each quad ----
    #pragma unroll
    for (int r = 0; r < 8; ++r) {
        #pragma unroll
        for (int off = 1; off < 4; off <<= 1) {
            float ov1 = __shfl_xor_sync(0xffffffffu, v1[r], off);
            float ov2 = __shfl_xor_sync(0xffffffffu, v2[r], off);
            int   oi  = __shfl_xor_sync(0xffffffffu, i1[r], off);
            float lo = fminf(v1[r], ov1);
            float hi = fmaxf(v1[r], ov1);
            float s2 = fminf(fminf(v2[r], ov2), hi);
            if (ov1 < v1[r] || (ov1 == v1[r] && oi < i1[r])) i1[r] = oi;
            v1[r] = lo; v2[r] = s2;
        }
    }

    // ---- cross-warp merge via smem, margin test ----
    float* mv1 = reinterpret_cast<float*>(sm + SM_MRG);
    float* mv2 = mv1 + 512;
    int*   mi  = reinterpret_cast<int*>(mv2 + 512);
    if ((lane & 3) == 0) {
        int q = lane >> 2;
        #pragma unroll
        for (int mf = 0; mf < 4; ++mf)
            #pragma unroll
            for (int dlt = 0; dlt < 2; ++dlt) {
                int row = mw * 64 + mf * 16 + dlt * 8 + q;
                int r = mf * 2 + dlt;
                mv1[nw * 128 + row] = v1[r];
                mv2[nw * 128 + row] = v2[r];
                mi [nw * 128 + row] = i1[r];
            }
    }
    __syncthreads();
    if (tid < 128) {
        float bv1 = mv1[tid], bv2 = mv2[tid];
        int   bi  = mi[tid];
        #pragma unroll
        for (int g = 1; g < 4; ++g) {
            float ov1 = mv1[g * 128 + tid], ov2 = mv2[g * 128 + tid];
            int   oi  = mi[g * 128 + tid];
            float lo = fminf(bv1, ov1);
            float hi = fmaxf(bv1, ov1);
            bv2 = fminf(fminf(bv2, ov2), hi);
            if (ov1 < bv1 || (ov1 == bv1 && oi < bi)) bi = oi;
            bv1 = lo;
        }
        int n = n0 + tid;
        if (__fsub_rn(bv2, bv1) > DELTA) {
            g_idx[n] = bi;                      // provably the reference argmin
        } else {
            g_idx[n] = -1;                      // marker: resolved via g_best
            g_best[n] = ~0ull;
            int p = atomicAdd(&g_ucount, 1);    // near-tie -> exact rescore
            g_ulist[p] = n;
        }
    }
}

// ============================ kernel 2: exact fallback (smem-staged, R12) ==
__global__ void __launch_bounds__(512)
vq_fallback_kernel(const float* __restrict__ z, const float* __restrict__ cb) {
    extern __shared__ float fsm[];
    float* cbs  = fsm;                            // [64 * 257]
    float* zrow = fsm + FB_CBS_FLOATS;            // [32][256]
    float* zsqs = zrow + FB_ROWS * 256;           // [32]
    int*   rown = reinterpret_cast<int*>(zsqs + FB_ROWS);   // [32]

    const int t = threadIdx.x;
    const int cnt = g_ucount;
    const int nbatch = (cnt + FB_ROWS - 1) / FB_ROWS;
    const int ntasks = nbatch * FB_CHUNKS;

    for (int task = blockIdx.x; task < ntasks; task += gridDim.x) {
        const int batch = task >> 4;              // FB_CHUNKS = 16
        const int chunk = task & 15;
        const int base  = batch * FB_ROWS;
        const int nr    = min(FB_ROWS, cnt - base);

        __syncthreads();                          // protect smem reuse
        if (t < FB_ROWS) rown[t] = g_ulist[base + min(t, nr - 1)];
        __syncthreads();
        for (int e = t; e < FB_ROWS * 256; e += 512) {
            int j = e >> 8, d = e & 255;
            int n = rown[j], bb = n >> 10, hw = n & 1023;
            zrow[j * 256 + d] = z[((size_t)bb * 256 + d) * 1024 + hw];
        }
        __syncthreads();
        {
            int wj = t >> 5, lane = t & 31;
            for (int rr = wj; rr < FB_ROWS; rr += 16) {
                float s = 0.0f;
                #pragma unroll
                for (int j = 0; j < 8; ++j) {
                    float v = zrow[rr * 256 + lane + 32 * j];
                    s = fmaf(v, v, s);
                }
                #pragma unroll
                for (int o = 16; o > 0; o >>= 1) s += __shfl_down_sync(0xffffffffu, s, o);
                if (lane == 0) zsqs[rr] = s;
            }
        }
        __syncthreads();

        const int c    = t & 63;
        const int slot = t >> 6;                  // rows slot*4 .. slot*4+3
        const int j0   = slot * 4;

        for (int st = 0; st < FB_NSTAGE; ++st) {
            const int k0 = chunk * FB_CODES + st * FB_STAGE;
            const float4* cb4 = reinterpret_cast<const float4*>(cb);
            #pragma unroll
            for (int ii = 0; ii < 8; ++ii) {
                int idx = t + ii * 512;           // 0..4095
                int row = idx >> 6, q = idx & 63;
                float4 v = cb4[(size_t)(k0 + row) * 64 + q];
                float* dstp = &cbs[row * 257 + q * 4];
                dstp[0] = v.x; dstp[1] = v.y; dstp[2] = v.z; dstp[3] = v.w;
            }
            __syncthreads();

            float dot0 = 0.0f, dot1 = 0.0f, dot2 = 0.0f, dot3 = 0.0f;
            const float* cc = &cbs[c * 257];
            const float* z0 = &zrow[(j0 + 0) * 256];
            const float* z1 = &zrow[(j0 + 1) * 256];
            const float* z2 = &zrow[(j0 + 2) * 256];
            const float* z3 = &zrow[(j0 + 3) * 256];
            #pragma unroll 8
            for (int d = 0; d < 256; ++d) {
                float e = cc[d];
                dot0 = fmaf(z0[d], e, dot0);
                dot1 = fmaf(z1[d], e, dot1);
                dot2 = fmaf(z2[d], e, dot2);
                dot3 = fmaf(z3[d], e, dot3);
            }
            const int k = k0 + c;
            const float es = g_esq[k];
            float dist[4];
            dist[0] = __fadd_rn(__fsub_rn(zsqs[j0 + 0], __fmul_rn(2.0f, dot0)), es);
            dist[1] = __fadd_rn(__fsub_rn(zsqs[j0 + 1], __fmul_rn(2.0f, dot1)), es);
            dist[2] = __fadd_rn(__fsub_rn(zsqs[j0 + 2], __fmul_rn(2.0f, dot2)), es);
            dist[3] = __fadd_rn(__fsub_rn(zsqs[j0 + 3], __fmul_rn(2.0f, dot3)), es);
            #pragma unroll
            for (int j = 0; j < 4; ++j) {
                unsigned long long p =
                    ((unsigned long long)__float_as_uint(dist[j]) << 32) | (unsigned)k;
                #pragma unroll
                for (int o = 16; o > 0; o >>= 1) {
                    unsigned long long op = __shfl_xor_sync(0xffffffffu, p, o);
                    if (op < p) p = op;
                }
                if ((t & 31) == 0 && (j0 + j) < nr)
                    atomicMin(&g_best[rown[j0 + j]], p);
            }
            __syncthreads();
        }
    }
}

// ============================ kernel 3: output epilogue (two-phase) ========
// Resolves fallback rows inline: g_idx[n] < 0 -> index in g_best[n] low bits.
__global__ void __launch_bounds__(EP_THREADS)
vq_epilogue_kernel(const float* __restrict__ z, const float* __restrict__ cb,
                   float* __restrict__ out, int out_size) {
    extern __shared__ float zq[];                 // [64][EP_STRIDE]
    __shared__ int idx_s[EP_ROWS];
    __shared__ double red[EP_THREADS];

    const int t  = threadIdx.x;
    const int n0 = blockIdx.x * EP_ROWS;

    if (t < EP_ROWS) {
        int n = n0 + t;
        int ii = g_idx[n];
        if (ii < 0) ii = (int)(g_best[n] & 0xffffffffu);   // fused resolve
        idx_s[t] = ii;
        int oi = IDX_OFF + n;
        if (oi < out_size) out[oi] = (float)ii;
    }
    __syncthreads();

    {
        const int wj   = t >> 5;
        const int lane = t & 31;
        #pragma unroll
        for (int rr = 0; rr < 8; ++rr) {
            int row = wj * 8 + rr;
            const float4* src = reinterpret_cast<const float4*>(
                cb + (size_t)idx_s[row] * DIMS);
            float4 q0 = src[lane];
            float4 q1 = src[lane + 32];
            float* dst = &zq[row * EP_STRIDE];
            *reinterpret_cast<float4*>(dst + lane * 4)       = q0;
            *reinterpret_cast<float4*>(dst + 128 + lane * 4) = q1;
        }
    }
    __syncthreads();

    const int b   = n0 >> 10;
    const int hw0 = n0 & 1023;
    const float* zb = z + ((size_t)b * 256) * 1024 + hw0;
    float*       ob = out + ((size_t)b * 256) * 1024 + hw0;

    const int r  = t & 63;
    const int dq = t >> 6;
    const float* qrow = &zq[r * EP_STRIDE];

    double accd = 0.0;
    #pragma unroll 8
    for (int p = 0; p < 64; ++p) {
        int d = dq * 64 + p;
        float qv = qrow[d];
        float zv = zb[(size_t)d * 1024 + r];
        float diff = __fsub_rn(qv, zv);
        ob[(size_t)d * 1024 + r] = __fadd_rn(zv, diff);   // straight-through
        accd = fma((double)diff, (double)diff, accd);
    }

    red[t] = accd;
    __syncthreads();
    for (int s = EP_THREADS / 2; s > 0; s >>= 1) {
        if (t < s) red[t] += red[t + s];
        __syncthreads();
    }
    if (t == 0) g_partials[blockIdx.x] = red[0];
}

// ============================ kernel 4: finalize loss ======================
__global__ void vq_finalize_kernel(float* __restrict__ out, int out_size) {
    __shared__ double red[256];
    const int t = threadIdx.x;
    red[t] = g_partials[t] + g_partials[t + 256];
    __syncthreads();
    for (int s = 128; s > 0; s >>= 1) {
        if (t < s) red[t] += red[t + s];
        __syncthreads();
    }
    if (t == 0 && LOSS_OFF < out_size) {
        double mean = red[0] / (double)ZELEMS;
        float m = (float)mean;
        out[LOSS_OFF] = __fadd_rn(m, __fmul_rn(0.25f, m));
    }
}

// ============================ launch ======================================
extern "C" void kernel_launch(void* const* d_in, const int* in_sizes, int n_in,
                              void* d_out, int out_size) {
    const float* z  = (const float*)d_in[0];
    const float* cb = (const float*)d_in[1];
    if (n_in >= 2 && in_sizes[0] == KCODES * DIMS && in_sizes[1] == ZELEMS) {
        const float* tmp = z; z = cb; cb = tmp;
    }
    float* out = (float*)d_out;

    cudaFuncSetAttribute(vq_mma_kernel,
                         cudaFuncAttributeMaxDynamicSharedMemorySize, SM_TOTAL);
    cudaFuncSetAttribute(vq_fallback_kernel,
                         cudaFuncAttributeMaxDynamicSharedMemorySize, FB_SMEM);
    cudaFuncSetAttribute(vq_epilogue_kernel,
                         cudaFuncAttributeMaxDynamicSharedMemorySize, EP_SMEM);

    vq_cbprep<<<KCODES / 8, 256>>>(cb);
    vq_mma_kernel<<<NMMACTA, 256, SM_TOTAL>>>(z);
    vq_fallback_kernel<<<256, 512, FB_SMEM>>>(z, cb);
    vq_epilogue_kernel<<<EP_NCTA, EP_THREADS, EP_SMEM>>>(z, cb, out, out_size);
    vq_finalize_kernel<<<1, 256>>>(out, out_size);
}

// round 16
// speedup vs baseline: 1.7392x; 1.0993x over previous
#include <cuda_runtime.h>
#include <cuda_fp16.h>
#include <float.h>
#include <stdint.h>

// ============================ problem constants ============================
#define KCODES   4096
#define DIMS     256
#define NROWS    32768
#define ZELEMS   8388608
#define LOSS_OFF 8388608
#define IDX_OFF  8388609

// ============================ main GEMM config (R13 geometry, frozen) ======
#define MT          128                  // z rows per CTA
#define NMMACTA     (NROWS / MT)         // 256 CTAs
#define NCODE       128                  // codes per chunk
#define NCHUNKS     (KCODES / NCODE)     // 32
#define DELTA       3.0e-4f              // provable-argmin margin (fp16 approx)

#define ROW_BYTES   528                  // 256 fp16 + 16B pad (LDSM conflict-free)
#define TILE_BYTES  (128 * ROW_BYTES)    // 67584 per A / B buffer
#define SM_A        0
#define SM_B0       TILE_BYTES
#define SM_B1       (2 * TILE_BYTES)
#define SM_MRG      (3 * TILE_BYTES)     // 2*512 floats + 512 ints = 6144
#define SM_TOTAL    (3 * TILE_BYTES + 6144)   // 208896 bytes

// fallback: 32-row batches x 256-code chunks, 64-code smem stages (R12)
#define FB_ROWS   32
#define FB_CODES  256
#define FB_CHUNKS (KCODES / FB_CODES)    // 16
#define FB_STAGE  64
#define FB_NSTAGE (FB_CODES / FB_STAGE)  // 4
#define FB_CBS_FLOATS (FB_STAGE * 257)   // 16448
#define FB_SMEM  ((FB_CBS_FLOATS + FB_ROWS * 256 + FB_ROWS) * 4 + FB_ROWS * 4)

// epilogue kernel tiling
#define EP_ROWS   64
#define EP_NCTA   (NROWS / EP_ROWS)      // 512
#define EP_THREADS 256
#define EP_STRIDE 260                    // floats; multiple of 4 -> aligned float4
#define EP_SMEM   (EP_ROWS * EP_STRIDE * 4)   // 66560 bytes dynamic

// ============================ device globals ===============================
__device__ float  g_esq[KCODES];
__device__ int    g_idx[NROWS];
__device__ double g_partials[EP_NCTA];
__device__ __align__(16) __half g_cbh[KCODES * DIMS];      // codebook fp16
__device__ int g_ucount;
__device__ int g_ulist[NROWS];
__device__ unsigned long long g_best[NROWS];               // packed (dist,k)

// ============================ PTX helpers ==================================
__device__ __forceinline__ uint32_t smem_u32(const void* p) {
    uint32_t a;
    asm("{ .reg .u64 t; cvta.to.shared.u64 t, %1; cvt.u32.u64 %0, t; }"
        : "=r"(a) : "l"(p));
    return a;
}

#define CP_ASYNC16(dst, src) \
    asm volatile("cp.async.cg.shared.global [%0], [%1], 16;" \
                 :: "r"(dst), "l"(src) : "memory")
#define CP_COMMIT() asm volatile("cp.async.commit_group;" ::: "memory")
#define CP_WAIT(n)  asm volatile("cp.async.wait_group %0;" :: "n"(n) : "memory")

#define LDSM_X4(r0, r1, r2, r3, addr) \
    asm volatile("ldmatrix.sync.aligned.m8n8.x4.shared.b16 {%0,%1,%2,%3}, [%4];" \
                 : "=r"(r0), "=r"(r1), "=r"(r2), "=r"(r3) : "r"(addr))

#define MMA_F16(acc, a, b0, b1) \
    asm volatile("mma.sync.aligned.m16n8k16.row.col.f32.f16.f16.f32 " \
        "{%0,%1,%2,%3}, {%4,%5,%6,%7}, {%8,%9}, {%0,%1,%2,%3};" \
        : "+f"((acc)[0]), "+f"((acc)[1]), "+f"((acc)[2]), "+f"((acc)[3]) \
        : "r"((a)[0]), "r"((a)[1]), "r"((a)[2]), "r"((a)[3]), \
          "r"(b0), "r"(b1))

__device__ __forceinline__ uint32_t pack_f16x2(float a0, float a1) {
    __half2 h2 = __floats2half2_rn(a0, a1);
    return *reinterpret_cast<uint32_t*>(&h2);
}

// ============== kernel 0: cb -> fp16 + e_sq + counter reset (merged) =======
__global__ void vq_cbprep(const float* __restrict__ cb) {
    const int warp = blockIdx.x * 8 + (threadIdx.x >> 5);
    const int lane = threadIdx.x & 31;
    if (blockIdx.x == 0 && threadIdx.x == 0) g_ucount = 0;
    if (warp >= KCODES) return;
    const float4* row = reinterpret_cast<const float4*>(cb) + (size_t)warp * 64;
    float4 v0 = row[lane];
    float4 v1 = row[lane + 32];
    float s = 0.0f;
    s = fmaf(v0.x, v0.x, s); s = fmaf(v0.y, v0.y, s);
    s = fmaf(v0.z, v0.z, s); s = fmaf(v0.w, v0.w, s);
    s = fmaf(v1.x, v1.x, s); s = fmaf(v1.y, v1.y, s);
    s = fmaf(v1.z, v1.z, s); s = fmaf(v1.w, v1.w, s);
    uint2 p0, p1;
    p0.x = pack_f16x2(v0.x, v0.y); p0.y = pack_f16x2(v0.z, v0.w);
    p1.x = pack_f16x2(v1.x, v1.y); p1.y = pack_f16x2(v1.z, v1.w);
    uint2* dst = reinterpret_cast<uint2*>(g_cbh + (size_t)warp * DIMS);
    dst[lane]      = p0;
    dst[lane + 32] = p1;
    #pragma unroll
    for (int o = 16; o > 0; o >>= 1) s += __shfl_down_sync(0xffffffffu, s, o);
    if (lane == 0) g_esq[warp] = s;
}

// ============================ kernel 1: HMMA GEMM + margin argmin ==========
// R13 geometry; dist pass now branch-free (FMNMX/SEL) — identical values,
// identical first-index tie-break, fewer issue slots competing with HMMA.
__global__ void __launch_bounds__(256, 1)
vq_mma_kernel(const float* __restrict__ z) {
    extern __shared__ char sm[];
    const uint32_t smb = smem_u32(sm);
    const int tid  = threadIdx.x;
    const int lane = tid & 31;
    const int w    = tid >> 5;
    const int mw   = w & 1;
    const int nw   = w >> 1;
    const int n0   = blockIdx.x * MT;
    const int b    = n0 >> 10;
    const int hw0  = n0 & 1023;

    // ---- stage B chunk 0 first (async), then convert A while B streams ----
    {
        const char* srcB = (const char*)g_cbh;
        #pragma unroll
        for (int i = 0; i < 16; ++i) {
            int seg = tid + i * 256;
            int rc = seg >> 5, s = seg & 31;
            CP_ASYNC16(smb + SM_B0 + rc * ROW_BYTES + s * 16,
                       srcB + (size_t)rc * 512 + s * 16);
        }
        CP_COMMIT();
    }
    // ---- stage A: z fp32 -> fp16 row-major in smem ----
    {
        const int r   = tid & 127;
        const int seg = tid >> 7;                // 0..1, 128 d's each
        const float* zp = z + ((size_t)b * 256 + seg * 128) * 1024 + hw0 + r;
        #pragma unroll
        for (int i = 0; i < 16; ++i) {
            uint4 q;
            uint32_t* qs = reinterpret_cast<uint32_t*>(&q);
            #pragma unroll
            for (int j = 0; j < 4; ++j) {
                float a0 = zp[(size_t)(i * 8 + 2 * j) * 1024];
                float a1 = zp[(size_t)(i * 8 + 2 * j + 1) * 1024];
                qs[j] = pack_f16x2(a0, a1);
            }
            *reinterpret_cast<uint4*>(sm + SM_A + r * ROW_BYTES
                                      + seg * 256 + i * 16) = q;
        }
    }

    const uint32_t lr = (uint32_t)((lane & 7) + ((lane >> 3) & 1) * 8);
    const uint32_t ch = (uint32_t)((lane >> 4) & 1);
    const uint32_t a_base = smb + SM_A + (mw * 64 + lr) * ROW_BYTES + ch * 16;
    const uint32_t b_off  = (nw * 32 + lr) * ROW_BYTES + ch * 16;

    float v1[8], v2[8]; int i1[8];
    #pragma unroll
    for (int r = 0; r < 8; ++r) { v1[r] = FLT_MAX; v2[r] = FLT_MAX; i1[r] = 0; }

    for (int c = 0; c < NCHUNKS; ++c) {
        if (c < NCHUNKS - 1) {
            const char* srcB = (const char*)g_cbh + (size_t)(c + 1) * NCODE * 512;
            uint32_t dstB = smb + (((c + 1) & 1) ? SM_B1 : SM_B0);
            #pragma unroll
            for (int i = 0; i < 16; ++i) {
                int seg = tid + i * 256;
                int rc = seg >> 5, s = seg & 31;
                CP_ASYNC16(dstB + rc * ROW_BYTES + s * 16,
                           srcB + (size_t)rc * 512 + s * 16);
            }
            CP_COMMIT();
            CP_WAIT(1);
        } else {
            CP_WAIT(0);
        }
        __syncthreads();

        const uint32_t bbuf = smb + ((c & 1) ? SM_B1 : SM_B0);

        float acc[4][4][4];
        #pragma unroll
        for (int mf = 0; mf < 4; ++mf)
            #pragma unroll
            for (int nf = 0; nf < 4; ++nf)
                #pragma unroll
                for (int i = 0; i < 4; ++i) acc[mf][nf][i] = 0.0f;

        #pragma unroll
        for (int ks = 0; ks < 16; ++ks) {
            uint32_t a[4][4];
            #pragma unroll
            for (int mf = 0; mf < 4; ++mf)
                LDSM_X4(a[mf][0], a[mf][1], a[mf][2], a[mf][3],
                        a_base + mf * (16 * ROW_BYTES) + ks * 32);
            uint32_t bf[2][4];
            #pragma unroll
            for (int p = 0; p < 2; ++p)
                LDSM_X4(bf[p][0], bf[p][1], bf[p][2], bf[p][3],
                        bbuf + b_off + p * (16 * ROW_BYTES) + ks * 32);
            #pragma unroll
            for (int mf = 0; mf < 4; ++mf) {
                #pragma unroll
                for (int p = 0; p < 2; ++p) {
                    MMA_F16(acc[mf][p * 2 + 0], a[mf], bf[p][0], bf[p][2]);
                    MMA_F16(acc[mf][p * 2 + 1], a[mf], bf[p][1], bf[p][3]);
                }
            }
        }

        // ---- shifted dists + branch-free (best, second-best) update ----
        const int kbase = c * NCODE + nw * 32;
        #pragma unroll
        for (int nf = 0; nf < 4; ++nf) {
            int kc = kbase + nf * 8 + (lane & 3) * 2;
            float2 e2 = *reinterpret_cast<const float2*>(&g_esq[kc]);
            #pragma unroll
            for (int mf = 0; mf < 4; ++mf) {
                #pragma unroll
                for (int i = 0; i < 4; ++i) {
                    int ri = mf * 2 + (i >> 1);
                    float e = (i & 1) ? e2.y : e2.x;
                    float d = fmaf(-2.0f, acc[mf][nf][i], e);
                    // identical values to the branchy version:
                    // new v2 = min(v2, max(v1, d)); v1 = min(v1, d);
                    // i1 updates only on strict d < v1 (first-index ties).
                    float ov1 = v1[ri];
                    v2[ri] = fminf(v2[ri], fmaxf(ov1, d));
                    i1[ri] = (d < ov1) ? (kc + (i & 1)) : i1[ri];
                    v1[ri] = fminf(ov1, d);
                }
            }
        }
        __syncthreads();
    }

    // ---- merge across the 4 lanes of each quad ----
    #pragma unroll
    for (int r = 0; r < 8; ++r) {
        #pragma unroll
        for (int off = 1; off < 4; off <<= 1) {
            float ov1 = __shfl_xor_sync(0xffffffffu, v1[r], off);
            float ov2 = __shfl_xor_sync(0xffffffffu, v2[r], off);
            int   oi  = __shfl_xor_sync(0xffffffffu, i1[r], off);
            float lo = fminf(v1[r], ov1);
            float hi = fmaxf(v1[r], ov1);
            float s2 = fminf(fminf(v2[r], ov2), hi);
            if (ov1 < v1[r] || (ov1 == v1[r] && oi < i1[r])) i1[r] = oi;
            v1[r] = lo; v2[r] = s2;
        }
    }

    // ---- cross-warp merge via smem, margin test ----
    float* mv1 = reinterpret_cast<float*>(sm + SM_MRG);
    float* mv2 = mv1 + 512;
    int*   mi  = reinterpret_cast<int*>(mv2 + 512);
    if ((lane & 3) == 0) {
        int q = lane >> 2;
        #pragma unroll
        for (int mf = 0; mf < 4; ++mf)
            #pragma unroll
            for (int dlt = 0; dlt < 2; ++dlt) {
                int row = mw * 64 + mf * 16 + dlt * 8 + q;
                int r = mf * 2 + dlt;
                mv1[nw * 128 + row] = v1[r];
                mv2[nw * 128 + row] = v2[r];
                mi [nw * 128 + row] = i1[r];
            }
    }
    __syncthreads();
    if (tid < 128) {
        float bv1 = mv1[tid], bv2 = mv2[tid];
        int   bi  = mi[tid];
        #pragma unroll
        for (int g = 1; g < 4; ++g) {
            float ov1 = mv1[g * 128 + tid], ov2 = mv2[g * 128 + tid];
            int   oi  = mi[g * 128 + tid];
            float lo = fminf(bv1, ov1);
            float hi = fmaxf(bv1, ov1);
            bv2 = fminf(fminf(bv2, ov2), hi);
            if (ov1 < bv1 || (ov1 == bv1 && oi < bi)) bi = oi;
            bv1 = lo;
        }
        int n = n0 + tid;
        if (__fsub_rn(bv2, bv1) > DELTA) {
            g_idx[n] = bi;                      // provably the reference argmin
        } else {
            g_idx[n] = -1;                      // marker: resolved via g_best
            g_best[n] = ~0ull;
            int p = atomicAdd(&g_ucount, 1);    // near-tie -> exact rescore
            g_ulist[p] = n;
        }
    }
}

// ============================ kernel 2: exact fallback (smem-staged, R12) ==
__global__ void __launch_bounds__(512)
vq_fallback_kernel(const float* __restrict__ z, const float* __restrict__ cb) {
    extern __shared__ float fsm[];
    float* cbs  = fsm;                            // [64 * 257]
    float* zrow = fsm + FB_CBS_FLOATS;            // [32][256]
    float* zsqs = zrow + FB_ROWS * 256;           // [32]
    int*   rown = reinterpret_cast<int*>(zsqs + FB_ROWS);   // [32]

    const int t = threadIdx.x;
    const int cnt = g_ucount;
    const int nbatch = (cnt + FB_ROWS - 1) / FB_ROWS;
    const int ntasks = nbatch * FB_CHUNKS;

    for (int task = blockIdx.x; task < ntasks; task += gridDim.x) {
        const int batch = task >> 4;              // FB_CHUNKS = 16
        const int chunk = task & 15;
        const int base  = batch * FB_ROWS;
        const int nr    = min(FB_ROWS, cnt - base);

        __syncthreads();                          // protect smem reuse
        if (t < FB_ROWS) rown[t] = g_ulist[base + min(t, nr - 1)];
        __syncthreads();
        for (int e = t; e < FB_ROWS * 256; e += 512) {
            int j = e >> 8, d = e & 255;
            int n = rown[j], bb = n >> 10, hw = n & 1023;
            zrow[j * 256 + d] = z[((size_t)bb * 256 + d) * 1024 + hw];
        }
        __syncthreads();
        {
            int wj = t >> 5, lane = t & 31;
            for (int rr = wj; rr < FB_ROWS; rr += 16) {
                float s = 0.0f;
                #pragma unroll
                for (int j = 0; j < 8; ++j) {
                    float v = zrow[rr * 256 + lane + 32 * j];
                    s = fmaf(v, v, s);
                }
                #pragma unroll
                for (int o = 16; o > 0; o >>= 1) s += __shfl_down_sync(0xffffffffu, s, o);
                if (lane == 0) zsqs[rr] = s;
            }
        }
        __syncthreads();

        const int c    = t & 63;
        const int slot = t >> 6;                  // rows slot*4 .. slot*4+3
        const int j0   = slot * 4;

        for (int st = 0; st < FB_NSTAGE; ++st) {
            const int k0 = chunk * FB_CODES + st * FB_STAGE;
            const float4* cb4 = reinterpret_cast<const float4*>(cb);
            #pragma unroll
            for (int ii = 0; ii < 8; ++ii) {
                int idx = t + ii * 512;           // 0..4095
                int row = idx >> 6, q = idx & 63;
                float4 v = cb4[(size_t)(k0 + row) * 64 + q];
                float* dstp = &cbs[row * 257 + q * 4];
                dstp[0] = v.x; dstp[1] = v.y; dstp[2] = v.z; dstp[3] = v.w;
            }
            __syncthreads();

            float dot0 = 0.0f, dot1 = 0.0f, dot2 = 0.0f, dot3 = 0.0f;
            const float* cc = &cbs[c * 257];
            const float* z0 = &zrow[(j0 + 0) * 256];
            const float* z1 = &zrow[(j0 + 1) * 256];
            const float* z2 = &zrow[(j0 + 2) * 256];
            const float* z3 = &zrow[(j0 + 3) * 256];
            #pragma unroll 8
            for (int d = 0; d < 256; ++d) {
                float e = cc[d];
                dot0 = fmaf(z0[d], e, dot0);
                dot1 = fmaf(z1[d], e, dot1);
                dot2 = fmaf(z2[d], e, dot2);
                dot3 = fmaf(z3[d], e, dot3);
            }
            const int k = k0 + c;
            const float es = g_esq[k];
            float dist[4];
            dist[0] = __fadd_rn(__fsub_rn(zsqs[j0 + 0], __fmul_rn(2.0f, dot0)), es);
            dist[1] = __fadd_rn(__fsub_rn(zsqs[j0 + 1], __fmul_rn(2.0f, dot1)), es);
            dist[2] = __fadd_rn(__fsub_rn(zsqs[j0 + 2], __fmul_rn(2.0f, dot2)), es);
            dist[3] = __fadd_rn(__fsub_rn(zsqs[j0 + 3], __fmul_rn(2.0f, dot3)), es);
            #pragma unroll
            for (int j = 0; j < 4; ++j) {
                unsigned long long p =
                    ((unsigned long long)__float_as_uint(dist[j]) << 32) | (unsigned)k;
                #pragma unroll
                for (int o = 16; o > 0; o >>= 1) {
                    unsigned long long op = __shfl_xor_sync(0xffffffffu, p, o);
                    if (op < p) p = op;
                }
                if ((t & 31) == 0 && (j0 + j) < nr)
                    atomicMin(&g_best[rown[j0 + j]], p);
            }
            __syncthreads();
        }
    }
}

// ============================ kernel 3: output epilogue ====================
// Two-phase, with fused resolve and batched-MLP streaming (16 loads in
// flight per thread -> latency hidden; arithmetic unchanged).
__global__ void __launch_bounds__(EP_THREADS)
vq_epilogue_kernel(const float* __restrict__ z, const float* __restrict__ cb,
                   float* __restrict__ out, int out_size) {
    extern __shared__ float zq[];                 // [64][EP_STRIDE]
    __shared__ int idx_s[EP_ROWS];
    __shared__ double red[EP_THREADS];

    const int t  = threadIdx.x;
    const int n0 = blockIdx.x * EP_ROWS;

    if (t < EP_ROWS) {
        int n = n0 + t;
        int ii = g_idx[n];
        if (ii < 0) ii = (int)(g_best[n] & 0xffffffffu);   // fused resolve
        idx_s[t] = ii;
        int oi = IDX_OFF + n;
        if (oi < out_size) out[oi] = (float)ii;
    }
    __syncthreads();

    {
        const int wj   = t >> 5;
        const int lane = t & 31;
        #pragma unroll
        for (int rr = 0; rr < 8; ++rr) {
            int row = wj * 8 + rr;
            const float4* src = reinterpret_cast<const float4*>(
                cb + (size_t)idx_s[row] * DIMS);
            float4 q0 = src[lane];
            float4 q1 = src[lane + 32];
            float* dst = &zq[row * EP_STRIDE];
            *reinterpret_cast<float4*>(dst + lane * 4)       = q0;
            *reinterpret_cast<float4*>(dst + 128 + lane * 4) = q1;
        }
    }
    __syncthreads();

    const int b   = n0 >> 10;
    const int hw0 = n0 & 1023;
    const float* zb = z + ((size_t)b * 256) * 1024 + hw0;
    float*       ob = out + ((size_t)b * 256) * 1024 + hw0;

    const int r  = t & 63;
    const int dq = t >> 6;                 // thread owns d in [dq*64, dq*64+64)
    const float* qrow = &zq[r * EP_STRIDE];

    double accd = 0.0;
    #pragma unroll
    for (int g2 = 0; g2 < 4; ++g2) {
        float zv[16];
        #pragma unroll
        for (int i = 0; i < 16; ++i)
            zv[i] = zb[(size_t)(dq * 64 + g2 * 16 + i) * 1024 + r];
        #pragma unroll
        for (int i = 0; i < 16; ++i) {
            int d = dq * 64 + g2 * 16 + i;
            float diff = __fsub_rn(qrow[d], zv[i]);
            ob[(size_t)d * 1024 + r] = __fadd_rn(zv[i], diff);  // straight-through
            accd = fma((double)diff, (double)diff, accd);
        }
    }

    red[t] = accd;
    __syncthreads();
    for (int s = EP_THREADS / 2; s > 0; s >>= 1) {
        if (t < s) red[t] += red[t + s];
        __syncthreads();
    }
    if (t == 0) g_partials[blockIdx.x] = red[0];
}

// ============================ kernel 4: finalize loss ======================
__global__ void vq_finalize_kernel(float* __restrict__ out, int out_size) {
    __shared__ double red[256];
    const int t = threadIdx.x;
    red[t] = g_partials[t] + g_partials[t + 256];
    __syncthreads();
    for (int s = 128; s > 0; s >>= 1) {
        if (t < s) red[t] += red[t + s];
        __syncthreads();
    }
    if (t == 0 && LOSS_OFF < out_size) {
        double mean = red[0] / (double)ZELEMS;
        float m = (float)mean;
        out[LOSS_OFF] = __fadd_rn(m, __fmul_rn(0.25f, m));
    }
}

// ============================ launch ======================================
extern "C" void kernel_launch(void* const* d_in, const int* in_sizes, int n_in,
                              void* d_out, int out_size) {
    const float* z  = (const float*)d_in[0];
    const float* cb = (const float*)d_in[1];
    if (n_in >= 2 && in_sizes[0] == KCODES * DIMS && in_sizes[1] == ZELEMS) {
        const float* tmp = z; z = cb; cb = tmp;
    }
    float* out = (float*)d_out;

    cudaFuncSetAttribute(vq_mma_kernel,
                         cudaFuncAttributeMaxDynamicSharedMemorySize, SM_TOTAL);
    cudaFuncSetAttribute(vq_fallback_kernel,
                         cudaFuncAttributeMaxDynamicSharedMemorySize, FB_SMEM);
    cudaFuncSetAttribute(vq_epilogue_kernel,
                         cudaFuncAttributeMaxDynamicSharedMemorySize, EP_SMEM);

    vq_cbprep<<<KCODES / 8, 256>>>(cb);
    vq_mma_kernel<<<NMMACTA, 256, SM_TOTAL>>>(z);
    vq_fallback_kernel<<<256, 512, FB_SMEM>>>(z, cb);
    vq_epilogue_kernel<<<EP_NCTA, EP_THREADS, EP_SMEM>>>(z, cb, out, out_size);
    vq_finalize_kernel<<<1, 256>>>(out, out_size);
}

// round 17
// speedup vs baseline: 1.7482x; 1.0052x over previous
#include <cuda_runtime.h>
#include <cuda_fp16.h>
#include <float.h>
#include <stdint.h>

// ============================ problem constants ============================
#define KCODES   4096
#define DIMS     256
#define NROWS    32768
#define ZELEMS   8388608
#define LOSS_OFF 8388608
#define IDX_OFF  8388609

// ============================ main GEMM config (R13 geometry, frozen) ======
#define MT          128                  // z rows per CTA
#define NMMACTA     (NROWS / MT)         // 256 CTAs
#define NCODE       128                  // codes per chunk
#define NCHUNKS     (KCODES / NCODE)     // 32
#define DELTA       3.0e-4f              // provable-argmin margin (fp16 approx)

#define ROW_BYTES   528                  // 256 fp16 + 16B pad (LDSM conflict-free)
#define TILE_BYTES  (128 * ROW_BYTES)    // 67584 per A / B buffer
#define SM_A        0
#define SM_B0       TILE_BYTES
#define SM_B1       (2 * TILE_BYTES)
#define SM_MRG      (3 * TILE_BYTES)     // 2*512 floats + 512 ints = 6144
#define SM_TOTAL    (3 * TILE_BYTES + 6144)   // 208896 bytes

// fallback: 32-row batches x 256-code chunks, 64-code smem stages (R12)
#define FB_ROWS   32
#define FB_CODES  256
#define FB_CHUNKS (KCODES / FB_CODES)    // 16
#define FB_STAGE  64
#define FB_NSTAGE (FB_CODES / FB_STAGE)  // 4
#define FB_CBS_FLOATS (FB_STAGE * 257)   // 16448
#define FB_SMEM  ((FB_CBS_FLOATS + FB_ROWS * 256 + FB_ROWS) * 4 + FB_ROWS * 4)

// epilogue kernel tiling
#define EP_ROWS   64
#define EP_NCTA   (NROWS / EP_ROWS)      // 512
#define EP_THREADS 256
#define EP_STRIDE 260                    // floats; multiple of 4 -> aligned float4
#define EP_SMEM   (EP_ROWS * EP_STRIDE * 4)   // 66560 bytes dynamic

// ============================ device globals ===============================
__device__ float  g_esq[KCODES];
__device__ int    g_idx[NROWS];
__device__ double g_partials[EP_NCTA];
__device__ __align__(16) __half g_cbh[KCODES * DIMS];      // codebook fp16
__device__ int g_ucount;
__device__ int g_ulist[NROWS];
__device__ unsigned long long g_best[NROWS];               // packed (dist,k)

// ============================ PTX helpers ==================================
__device__ __forceinline__ uint32_t smem_u32(const void* p) {
    uint32_t a;
    asm("{ .reg .u64 t; cvta.to.shared.u64 t, %1; cvt.u32.u64 %0, t; }"
        : "=r"(a) : "l"(p));
    return a;
}

#define CP_ASYNC16(dst, src) \
    asm volatile("cp.async.cg.shared.global [%0], [%1], 16;" \
                 :: "r"(dst), "l"(src) : "memory")
#define CP_COMMIT() asm volatile("cp.async.commit_group;" ::: "memory")
#define CP_WAIT(n)  asm volatile("cp.async.wait_group %0;" :: "n"(n) : "memory")

#define LDSM_X4(r0, r1, r2, r3, addr) \
    asm volatile("ldmatrix.sync.aligned.m8n8.x4.shared.b16 {%0,%1,%2,%3}, [%4];" \
                 : "=r"(r0), "=r"(r1), "=r"(r2), "=r"(r3) : "r"(addr))

#define MMA_F16(acc, a, b0, b1) \
    asm volatile("mma.sync.aligned.m16n8k16.row.col.f32.f16.f16.f32 " \
        "{%0,%1,%2,%3}, {%4,%5,%6,%7}, {%8,%9}, {%0,%1,%2,%3};" \
        : "+f"((acc)[0]), "+f"((acc)[1]), "+f"((acc)[2]), "+f"((acc)[3]) \
        : "r"((a)[0]), "r"((a)[1]), "r"((a)[2]), "r"((a)[3]), \
          "r"(b0), "r"(b1))

__device__ __forceinline__ uint32_t pack_f16x2(float a0, float a1) {
    __half2 h2 = __floats2half2_rn(a0, a1);
    return *reinterpret_cast<uint32_t*>(&h2);
}

// ============== kernel 0: cb -> fp16 + e_sq + counter reset (merged) =======
__global__ void vq_cbprep(const float* __restrict__ cb) {
    const int warp = blockIdx.x * 8 + (threadIdx.x >> 5);
    const int lane = threadIdx.x & 31;
    if (blockIdx.x == 0 && threadIdx.x == 0) g_ucount = 0;
    if (warp >= KCODES) return;
    const float4* row = reinterpret_cast<const float4*>(cb) + (size_t)warp * 64;
    float4 v0 = row[lane];
    float4 v1 = row[lane + 32];
    float s = 0.0f;
    s = fmaf(v0.x, v0.x, s); s = fmaf(v0.y, v0.y, s);
    s = fmaf(v0.z, v0.z, s); s = fmaf(v0.w, v0.w, s);
    s = fmaf(v1.x, v1.x, s); s = fmaf(v1.y, v1.y, s);
    s = fmaf(v1.z, v1.z, s); s = fmaf(v1.w, v1.w, s);
    uint2 p0, p1;
    p0.x = pack_f16x2(v0.x, v0.y); p0.y = pack_f16x2(v0.z, v0.w);
    p1.x = pack_f16x2(v1.x, v1.y); p1.y = pack_f16x2(v1.z, v1.w);
    uint2* dst = reinterpret_cast<uint2*>(g_cbh + (size_t)warp * DIMS);
    dst[lane]      = p0;
    dst[lane + 32] = p1;
    #pragma unroll
    for (int o = 16; o > 0; o >>= 1) s += __shfl_down_sync(0xffffffffu, s, o);
    if (lane == 0) g_esq[warp] = s;
}

// ============================ kernel 1: HMMA GEMM + margin argmin (R16) ====
__global__ void __launch_bounds__(256, 1)
vq_mma_kernel(const float* __restrict__ z) {
    extern __shared__ char sm[];
    const uint32_t smb = smem_u32(sm);
    const int tid  = threadIdx.x;
    const int lane = tid & 31;
    const int w    = tid >> 5;
    const int mw   = w & 1;
    const int nw   = w >> 1;
    const int n0   = blockIdx.x * MT;
    const int b    = n0 >> 10;
    const int hw0  = n0 & 1023;

    // ---- stage B chunk 0 first (async), then convert A while B streams ----
    {
        const char* srcB = (const char*)g_cbh;
        #pragma unroll
        for (int i = 0; i < 16; ++i) {
            int seg = tid + i * 256;
            int rc = seg >> 5, s = seg & 31;
            CP_ASYNC16(smb + SM_B0 + rc * ROW_BYTES + s * 16,
                       srcB + (size_t)rc * 512 + s * 16);
        }
        CP_COMMIT();
    }
    // ---- stage A: z fp32 -> fp16 row-major in smem ----
    {
        const int r   = tid & 127;
        const int seg = tid >> 7;                // 0..1, 128 d's each
        const float* zp = z + ((size_t)b * 256 + seg * 128) * 1024 + hw0 + r;
        #pragma unroll
        for (int i = 0; i < 16; ++i) {
            uint4 q;
            uint32_t* qs = reinterpret_cast<uint32_t*>(&q);
            #pragma unroll
            for (int j = 0; j < 4; ++j) {
                float a0 = zp[(size_t)(i * 8 + 2 * j) * 1024];
                float a1 = zp[(size_t)(i * 8 + 2 * j + 1) * 1024];
                qs[j] = pack_f16x2(a0, a1);
            }
            *reinterpret_cast<uint4*>(sm + SM_A + r * ROW_BYTES
                                      + seg * 256 + i * 16) = q;
        }
    }

    const uint32_t lr = (uint32_t)((lane & 7) + ((lane >> 3) & 1) * 8);
    const uint32_t ch = (uint32_t)((lane >> 4) & 1);
    const uint32_t a_base = smb + SM_A + (mw * 64 + lr) * ROW_BYTES + ch * 16;
    const uint32_t b_off  = (nw * 32 + lr) * ROW_BYTES + ch * 16;

    float v1[8], v2[8]; int i1[8];
    #pragma unroll
    for (int r = 0; r < 8; ++r) { v1[r] = FLT_MAX; v2[r] = FLT_MAX; i1[r] = 0; }

    for (int c = 0; c < NCHUNKS; ++c) {
        if (c < NCHUNKS - 1) {
            const char* srcB = (const char*)g_cbh + (size_t)(c + 1) * NCODE * 512;
            uint32_t dstB = smb + (((c + 1) & 1) ? SM_B1 : SM_B0);
            #pragma unroll
            for (int i = 0; i < 16; ++i) {
                int seg = tid + i * 256;
                int rc = seg >> 5, s = seg & 31;
                CP_ASYNC16(dstB + rc * ROW_BYTES + s * 16,
                           srcB + (size_t)rc * 512 + s * 16);
            }
            CP_COMMIT();
            CP_WAIT(1);
        } else {
            CP_WAIT(0);
        }
        __syncthreads();

        const uint32_t bbuf = smb + ((c & 1) ? SM_B1 : SM_B0);

        float acc[4][4][4];
        #pragma unroll
        for (int mf = 0; mf < 4; ++mf)
            #pragma unroll
            for (int nf = 0; nf < 4; ++nf)
                #pragma unroll
                for (int i = 0; i < 4; ++i) acc[mf][nf][i] = 0.0f;

        #pragma unroll
        for (int ks = 0; ks < 16; ++ks) {
            uint32_t a[4][4];
            #pragma unroll
            for (int mf = 0; mf < 4; ++mf)
                LDSM_X4(a[mf][0], a[mf][1], a[mf][2], a[mf][3],
                        a_base + mf * (16 * ROW_BYTES) + ks * 32);
            uint32_t bf[2][4];
            #pragma unroll
            for (int p = 0; p < 2; ++p)
                LDSM_X4(bf[p][0], bf[p][1], bf[p][2], bf[p][3],
                        bbuf + b_off + p * (16 * ROW_BYTES) + ks * 32);
            #pragma unroll
            for (int mf = 0; mf < 4; ++mf) {
                #pragma unroll
                for (int p = 0; p < 2; ++p) {
                    MMA_F16(acc[mf][p * 2 + 0], a[mf], bf[p][0], bf[p][2]);
                    MMA_F16(acc[mf][p * 2 + 1], a[mf], bf[p][1], bf[p][3]);
                }
            }
        }

        // ---- shifted dists + branch-free (best, second-best) update ----
        const int kbase = c * NCODE + nw * 32;
        #pragma unroll
        for (int nf = 0; nf < 4; ++nf) {
            int kc = kbase + nf * 8 + (lane & 3) * 2;
            float2 e2 = *reinterpret_cast<const float2*>(&g_esq[kc]);
            #pragma unroll
            for (int mf = 0; mf < 4; ++mf) {
                #pragma unroll
                for (int i = 0; i < 4; ++i) {
                    int ri = mf * 2 + (i >> 1);
                    float e = (i & 1) ? e2.y : e2.x;
                    float d = fmaf(-2.0f, acc[mf][nf][i], e);
                    float ov1 = v1[ri];
                    v2[ri] = fminf(v2[ri], fmaxf(ov1, d));
                    i1[ri] = (d < ov1) ? (kc + (i & 1)) : i1[ri];
                    v1[ri] = fminf(ov1, d);
                }
            }
        }
        __syncthreads();
    }

    // ---- merge across the 4 lanes of each quad ----
    #pragma unroll
    for (int r = 0; r < 8; ++r) {
        #pragma unroll
        for (int off = 1; off < 4; off <<= 1) {
            float ov1 = __shfl_xor_sync(0xffffffffu, v1[r], off);
            float ov2 = __shfl_xor_sync(0xffffffffu, v2[r], off);
            int   oi  = __shfl_xor_sync(0xffffffffu, i1[r], off);
            float lo = fminf(v1[r], ov1);
            float hi = fmaxf(v1[r], ov1);
            float s2 = fminf(fminf(v2[r], ov2), hi);
            if (ov1 < v1[r] || (ov1 == v1[r] && oi < i1[r])) i1[r] = oi;
            v1[r] = lo; v2[r] = s2;
        }
    }

    // ---- cross-warp merge via smem, margin test ----
    float* mv1 = reinterpret_cast<float*>(sm + SM_MRG);
    float* mv2 = mv1 + 512;
    int*   mi  = reinterpret_cast<int*>(mv2 + 512);
    if ((lane & 3) == 0) {
        int q = lane >> 2;
        #pragma unroll
        for (int mf = 0; mf < 4; ++mf)
            #pragma unroll
            for (int dlt = 0; dlt < 2; ++dlt) {
                int row = mw * 64 + mf * 16 + dlt * 8 + q;
                int r = mf * 2 + dlt;
                mv1[nw * 128 + row] = v1[r];
                mv2[nw * 128 + row] = v2[r];
                mi [nw * 128 + row] = i1[r];
            }
    }
    __syncthreads();
    if (tid < 128) {
        float bv1 = mv1[tid], bv2 = mv2[tid];
        int   bi  = mi[tid];
        #pragma unroll
        for (int g = 1; g < 4; ++g) {
            float ov1 = mv1[g * 128 + tid], ov2 = mv2[g * 128 + tid];
            int   oi  = mi[g * 128 + tid];
            float lo = fminf(bv1, ov1);
            float hi = fmaxf(bv1, ov1);
            bv2 = fminf(fminf(bv2, ov2), hi);
            if (ov1 < bv1 || (ov1 == bv1 && oi < bi)) bi = oi;
            bv1 = lo;
        }
        int n = n0 + tid;
        if (__fsub_rn(bv2, bv1) > DELTA) {
            g_idx[n] = bi;                      // provably the reference argmin
        } else {
            g_idx[n] = -1;                      // marker: resolved via g_best
            g_best[n] = ~0ull;
            int p = atomicAdd(&g_ucount, 1);    // near-tie -> exact rescore
            g_ulist[p] = n;
        }
    }
}

// ============================ kernel 2: exact fallback (smem-staged, R12) ==
__global__ void __launch_bounds__(512)
vq_fallback_kernel(const float* __restrict__ z, const float* __restrict__ cb) {
    extern __shared__ float fsm[];
    float* cbs  = fsm;                            // [64 * 257]
    float* zrow = fsm + FB_CBS_FLOATS;            // [32][256]
    float* zsqs = zrow + FB_ROWS * 256;           // [32]
    int*   rown = reinterpret_cast<int*>(zsqs + FB_ROWS);   // [32]

    const int t = threadIdx.x;
    const int cnt = g_ucount;
    const int nbatch = (cnt + FB_ROWS - 1) / FB_ROWS;
    const int ntasks = nbatch * FB_CHUNKS;

    for (int task = blockIdx.x; task < ntasks; task += gridDim.x) {
        const int batch = task >> 4;              // FB_CHUNKS = 16
        const int chunk = task & 15;
        const int base  = batch * FB_ROWS;
        const int nr    = min(FB_ROWS, cnt - base);

        __syncthreads();                          // protect smem reuse
        if (t < FB_ROWS) rown[t] = g_ulist[base + min(t, nr - 1)];
        __syncthreads();
        for (int e = t; e < FB_ROWS * 256; e += 512) {
            int j = e >> 8, d = e & 255;
            int n = rown[j], bb = n >> 10, hw = n & 1023;
            zrow[j * 256 + d] = z[((size_t)bb * 256 + d) * 1024 + hw];
        }
        __syncthreads();
        {
            int wj = t >> 5, lane = t & 31;
            for (int rr = wj; rr < FB_ROWS; rr += 16) {
                float s = 0.0f;
                #pragma unroll
                for (int j = 0; j < 8; ++j) {
                    float v = zrow[rr * 256 + lane + 32 * j];
                    s = fmaf(v, v, s);
                }
                #pragma unroll
                for (int o = 16; o > 0; o >>= 1) s += __shfl_down_sync(0xffffffffu, s, o);
                if (lane == 0) zsqs[rr] = s;
            }
        }
        __syncthreads();

        const int c    = t & 63;
        const int slot = t >> 6;                  // rows slot*4 .. slot*4+3
        const int j0   = slot * 4;

        for (int st = 0; st < FB_NSTAGE; ++st) {
            const int k0 = chunk * FB_CODES + st * FB_STAGE;
            const float4* cb4 = reinterpret_cast<const float4*>(cb);
            #pragma unroll
            for (int ii = 0; ii < 8; ++ii) {
                int idx = t + ii * 512;           // 0..4095
                int row = idx >> 6, q = idx & 63;
                float4 v = cb4[(size_t)(k0 + row) * 64 + q];
                float* dstp = &cbs[row * 257 + q * 4];
                dstp[0] = v.x; dstp[1] = v.y; dstp[2] = v.z; dstp[3] = v.w;
            }
            __syncthreads();

            float dot0 = 0.0f, dot1 = 0.0f, dot2 = 0.0f, dot3 = 0.0f;
            const float* cc = &cbs[c * 257];
            const float* z0 = &zrow[(j0 + 0) * 256];
            const float* z1 = &zrow[(j0 + 1) * 256];
            const float* z2 = &zrow[(j0 + 2) * 256];
            const float* z3 = &zrow[(j0 + 3) * 256];
            #pragma unroll 8
            for (int d = 0; d < 256; ++d) {
                float e = cc[d];
                dot0 = fmaf(z0[d], e, dot0);
                dot1 = fmaf(z1[d], e, dot1);
                dot2 = fmaf(z2[d], e, dot2);
                dot3 = fmaf(z3[d], e, dot3);
            }
            const int k = k0 + c;
            const float es = g_esq[k];
            float dist[4];
            dist[0] = __fadd_rn(__fsub_rn(zsqs[j0 + 0], __fmul_rn(2.0f, dot0)), es);
            dist[1] = __fadd_rn(__fsub_rn(zsqs[j0 + 1], __fmul_rn(2.0f, dot1)), es);
            dist[2] = __fadd_rn(__fsub_rn(zsqs[j0 + 2], __fmul_rn(2.0f, dot2)), es);
            dist[3] = __fadd_rn(__fsub_rn(zsqs[j0 + 3], __fmul_rn(2.0f, dot3)), es);
            #pragma unroll
            for (int j = 0; j < 4; ++j) {
                unsigned long long p =
                    ((unsigned long long)__float_as_uint(dist[j]) << 32) | (unsigned)k;
                #pragma unroll
                for (int o = 16; o > 0; o >>= 1) {
                    unsigned long long op = __shfl_xor_sync(0xffffffffu, p, o);
                    if (op < p) p = op;
                }
                if ((t & 31) == 0 && (j0 + j) < nr)
                    atomicMin(&g_best[rown[j0 + j]], p);
            }
            __syncthreads();
        }
    }
}

// ============================ kernel 3: output epilogue ====================
// Two-phase with fused resolve. Phase 2 re-mapped: thread owns 4 consecutive
// hw positions x 16 d values -> LDG.128/STG.128 streaming (4x bytes/instr in
// flight). Per-element arithmetic unchanged.
__global__ void __launch_bounds__(EP_THREADS)
vq_epilogue_kernel(const float* __restrict__ z, const float* __restrict__ cb,
                   float* __restrict__ out, int out_size) {
    extern __shared__ float zq[];                 // [64][EP_STRIDE]
    __shared__ int idx_s[EP_ROWS];
    __shared__ double red[EP_THREADS];

    const int t  = threadIdx.x;
    const int n0 = blockIdx.x * EP_ROWS;

    if (t < EP_ROWS) {
        int n = n0 + t;
        int ii = g_idx[n];
        if (ii < 0) ii = (int)(g_best[n] & 0xffffffffu);   // fused resolve
        idx_s[t] = ii;
        int oi = IDX_OFF + n;
        if (oi < out_size) out[oi] = (float)ii;
    }
    __syncthreads();

    // phase 1: 8 warps x 8 rows each, coalesced float4 reads of cb rows
    {
        const int wj   = t >> 5;
        const int lane = t & 31;
        #pragma unroll
        for (int rr = 0; rr < 8; ++rr) {
            int row = wj * 8 + rr;
            const float4* src = reinterpret_cast<const float4*>(
                cb + (size_t)idx_s[row] * DIMS);
            float4 q0 = src[lane];
            float4 q1 = src[lane + 32];
            float* dst = &zq[row * EP_STRIDE];
            *reinterpret_cast<float4*>(dst + lane * 4)       = q0;
            *reinterpret_cast<float4*>(dst + 128 + lane * 4) = q1;
        }
    }
    __syncthreads();

    const int b   = n0 >> 10;
    const int hw0 = n0 & 1023;
    const float* zb = z + ((size_t)b * 256) * 1024 + hw0;
    float*       ob = out + ((size_t)b * 256) * 1024 + hw0;

    // phase 2: thread (g2 = t&15 -> rows 4*g2..4*g2+3, dq = t>>4 -> d slice)
    const int g2 = t & 15;
    const int dq = t >> 4;                 // 0..15, d in [dq*16, dq*16+16)
    const int r0 = g2 * 4;

    double accd = 0.0;
    #pragma unroll
    for (int dd = 0; dd < 16; ++dd) {
        const int d = dq * 16 + dd;
        const float4 zv = *reinterpret_cast<const float4*>(
            &zb[(size_t)d * 1024 + r0]);
        const float q0 = zq[(r0 + 0) * EP_STRIDE + d];
        const float q1 = zq[(r0 + 1) * EP_STRIDE + d];
        const float q2 = zq[(r0 + 2) * EP_STRIDE + d];
        const float q3 = zq[(r0 + 3) * EP_STRIDE + d];
        float4 o;
        const float f0 = __fsub_rn(q0, zv.x); o.x = __fadd_rn(zv.x, f0);
        const float f1 = __fsub_rn(q1, zv.y); o.y = __fadd_rn(zv.y, f1);
        const float f2 = __fsub_rn(q2, zv.z); o.z = __fadd_rn(zv.z, f2);
        const float f3 = __fsub_rn(q3, zv.w); o.w = __fadd_rn(zv.w, f3);
        *reinterpret_cast<float4*>(&ob[(size_t)d * 1024 + r0]) = o;
        accd = fma((double)f0, (double)f0, accd);
        accd = fma((double)f1, (double)f1, accd);
        accd = fma((double)f2, (double)f2, accd);
        accd = fma((double)f3, (double)f3, accd);
    }

    red[t] = accd;
    __syncthreads();
    for (int s = EP_THREADS / 2; s > 0; s >>= 1) {
        if (t < s) red[t] += red[t + s];
        __syncthreads();
    }
    if (t == 0) g_partials[blockIdx.x] = red[0];
}

// ============================ kernel 4: finalize loss ======================
__global__ void vq_finalize_kernel(float* __restrict__ out, int out_size) {
    __shared__ double red[256];
    const int t = threadIdx.x;
    red[t] = g_partials[t] + g_partials[t + 256];
    __syncthreads();
    for (int s = 128; s > 0; s >>= 1) {
        if (t < s) red[t] += red[t + s];
        __syncthreads();
    }
    if (t == 0 && LOSS_OFF < out_size) {
        double mean = red[0] / (double)ZELEMS;
        float m = (float)mean;
        out[LOSS_OFF] = __fadd_rn(m, __fmul_rn(0.25f, m));
    }
}

// ============================ launch ======================================
extern "C" void kernel_launch(void* const* d_in, const int* in_sizes, int n_in,
                              void* d_out, int out_size) {
    const float* z  = (const float*)d_in[0];
    const float* cb = (const float*)d_in[1];
    if (n_in >= 2 && in_sizes[0] == KCODES * DIMS && in_sizes[1] == ZELEMS) {
        const float* tmp = z; z = cb; cb = tmp;
    }
    float* out = (float*)d_out;

    cudaFuncSetAttribute(vq_mma_kernel,
                         cudaFuncAttributeMaxDynamicSharedMemorySize, SM_TOTAL);
    cudaFuncSetAttribute(vq_fallback_kernel,
                         cudaFuncAttributeMaxDynamicSharedMemorySize, FB_SMEM);
    cudaFuncSetAttribute(vq_epilogue_kernel,
                         cudaFuncAttributeMaxDynamicSharedMemorySize, EP_SMEM);

    vq_cbprep<<<KCODES / 8, 256>>>(cb);
    vq_mma_kernel<<<NMMACTA, 256, SM_TOTAL>>>(z);
    vq_fallback_kernel<<<256, 512, FB_SMEM>>>(z, cb);
    vq_epilogue_kernel<<<EP_NCTA, EP_THREADS, EP_SMEM>>>(z, cb, out, out_size);
    vq_finalize_kernel<<<1, 256>>>(out, out_size);
}